// round 1
// baseline (speedup 1.0000x reference)
#include <cuda_runtime.h>
#include <cstdint>

#define DD 64
#define LL 128
#define KROWS 8192
#define RPB 64
#define NBLK (KROWS/RPB)
#define HSTR 68

__device__ float g_a[256];
__device__ float g_cb[256];
__device__ float g_Wt[64*256];
__device__ float g_acc[128];

__device__ __forceinline__ float fexp(float x){
    x = fmaxf(fminf(x, 30.f), -30.f);
    return __expf(x);
}
__device__ __forceinline__ float sigf(float x){
    return __fdividef(1.0f, 1.0f + fexp(-x));
}
__device__ __forceinline__ float tanhp(float x){
    return 2.0f * __fdividef(1.0f, 1.0f + fexp(-2.0f*x)) - 1.0f;
}

// Precompute collapsed input projection + transposed W_hh + zero accumulators.
__global__ void prep_kernel(const float* __restrict__ W_ih, const float* __restrict__ W_num,
                            const float* __restrict__ b_num, const float* __restrict__ b_ih,
                            const float* __restrict__ b_hh, const float* __restrict__ W_hh){
    int g = threadIdx.x;   // 0..255
    float sa = 0.f, sc = 0.f;
    #pragma unroll 8
    for (int d = 0; d < DD; d++){
        float w = W_ih[g*(2*DD)+d];
        sa += w * W_num[d];
        sc += w * b_num[d];
    }
    g_a[g]  = sa;
    g_cb[g] = sc + b_ih[g] + b_hh[g];
    #pragma unroll 8
    for (int k = 0; k < DD; k++) g_Wt[k*256+g] = W_hh[g*DD+k];
    if (g < 128) g_acc[g] = 0.f;
}

__global__ void __launch_bounds__(256,1)
lstm_kernel(const float* __restrict__ x,
            const float* __restrict__ W_aout, const float* __restrict__ b_aout,
            const float* __restrict__ W_fh,  const float* __restrict__ b_fh){
    extern __shared__ float sm[];
    float* sWt  = sm;                  // 16384 floats: Wt[k][g], k=0..63, g=0..255
    float* sH   = sm + 16384;          // 64*HSTR: h[d][r], stride HSTR
    float* sA   = sH + 64*HSTR;        // 256
    float* sC   = sA + 256;            // 256
    float* sRed = sC + 256;            // 128 (fc partial [0:64], hs partial [64:128])

    int tid = threadIdx.x;
    for (int i = tid; i < 16384;   i += 256) sWt[i] = g_Wt[i];
    for (int i = tid; i < 64*HSTR; i += 256) sH[i]  = 0.f;
    sA[tid] = g_a[tid];
    sC[tid] = g_cb[tid];
    if (tid < 128) sRed[tid] = 0.f;
    __syncthreads();

    const int tx = tid & 15;       // d-tile: d = tx*4 + j
    const int ty = tid >> 4;       // r-tile: r = ty*4 + i
    const int r0 = blockIdx.x * RPB;
    const float* xbase = x + (size_t)(r0 + ty*4) * LL;

    float cst[4][4];
    #pragma unroll
    for (int i = 0; i < 4; i++)
        #pragma unroll
        for (int j = 0; j < 4; j++) cst[i][j] = 0.f;

    for (int t = 0; t < LL; t++){
        float ai[4][4], af[4][4], ag[4][4], ao[4][4];
        #pragma unroll
        for (int i = 0; i < 4; i++)
            #pragma unroll
            for (int j = 0; j < 4; j++){ ai[i][j]=0.f; af[i][j]=0.f; ag[i][j]=0.f; ao[i][j]=0.f; }

        #pragma unroll 4
        for (int k = 0; k < DD; k++){
            float4 hv = *(const float4*)(sH + k*HSTR + (ty<<2));
            const float* wr = sWt + (k<<8);
            float4 wi = *(const float4*)(wr +       (tx<<2));
            float4 wf = *(const float4*)(wr +  64 + (tx<<2));
            float4 wg = *(const float4*)(wr + 128 + (tx<<2));
            float4 wo = *(const float4*)(wr + 192 + (tx<<2));
            float h[4] = {hv.x, hv.y, hv.z, hv.w};
            float vi[4] = {wi.x, wi.y, wi.z, wi.w};
            float vf[4] = {wf.x, wf.y, wf.z, wf.w};
            float vg[4] = {wg.x, wg.y, wg.z, wg.w};
            float vo[4] = {wo.x, wo.y, wo.z, wo.w};
            #pragma unroll
            for (int i = 0; i < 4; i++)
                #pragma unroll
                for (int j = 0; j < 4; j++){
                    ai[i][j] += h[i]*vi[j];
                    af[i][j] += h[i]*vf[j];
                    ag[i][j] += h[i]*vg[j];
                    ao[i][j] += h[i]*vo[j];
                }
        }
        __syncthreads();   // all reads of sH done

        float hn[4][4];
        #pragma unroll
        for (int i = 0; i < 4; i++){
            float xv = __ldg(xbase + i*LL + t);
            #pragma unroll
            for (int j = 0; j < 4; j++){
                int d = (tx<<2) + j;
                float gi = ai[i][j] + sA[d      ]*xv + sC[d      ];
                float gf = af[i][j] + sA[ 64 + d]*xv + sC[ 64 + d];
                float gg = ag[i][j] + sA[128 + d]*xv + sC[128 + d];
                float go = ao[i][j] + sA[192 + d]*xv + sC[192 + d];
                float c2 = sigf(gf)*cst[i][j] + sigf(gi)*tanhp(gg);
                cst[i][j] = c2;
                hn[i][j] = sigf(go)*tanhp(c2);
            }
        }
        #pragma unroll
        for (int j = 0; j < 4; j++){
            *(float4*)(sH + ((tx<<2)+j)*HSTR + (ty<<2)) =
                make_float4(hn[0][j], hn[1][j], hn[2][j], hn[3][j]);
        }
        __syncthreads();
    }

    // ----- final per-CTA stage: h_hat, f, partial reductions -----
    float* sHhat = sWt;            // [e][r] stride HSTR, 4352 floats
    float* sWa   = sWt + 8192;     // W_aout transposed: [e][d], 4096
    float* sWf   = sWt + 12288;    // W_fh  transposed: [e][d], 4096
    for (int i = tid; i < 4096; i += 256){
        int dd = i & 63;  // d
        int ee = i >> 6;  // e (k-dim)
        sWa[i] = W_aout[dd*64 + ee];
        sWf[i] = W_fh  [dd*64 + ee];
    }
    __syncthreads();

    // h_hat[r][d] = sum_e h[r][e] * W_aout[d][e] + b_aout[d]
    float hh[4][4];
    #pragma unroll
    for (int j = 0; j < 4; j++){
        float b = __ldg(b_aout + (tx<<2) + j);
        #pragma unroll
        for (int i = 0; i < 4; i++) hh[i][j] = b;
    }
    #pragma unroll 4
    for (int e = 0; e < DD; e++){
        float4 hv = *(const float4*)(sH + e*HSTR + (ty<<2));
        float4 wv = *(const float4*)(sWa + e*64 + (tx<<2));
        float h[4] = {hv.x, hv.y, hv.z, hv.w};
        float w[4] = {wv.x, wv.y, wv.z, wv.w};
        #pragma unroll
        for (int i = 0; i < 4; i++)
            #pragma unroll
            for (int j = 0; j < 4; j++) hh[i][j] += h[i]*w[j];
    }
    // stash h_hat transposed for the f GEMM; accumulate hs partials
    float hsb[4];
    #pragma unroll
    for (int j = 0; j < 4; j++){
        hsb[j] = hh[0][j] + hh[1][j] + hh[2][j] + hh[3][j];
        *(float4*)(sHhat + ((tx<<2)+j)*HSTR + (ty<<2)) =
            make_float4(hh[0][j], hh[1][j], hh[2][j], hh[3][j]);
    }
    __syncthreads();

    // f[r][d] = sum_e h_hat[r][e] * W_fh[d][e] + b_fh[d]
    float ff[4][4];
    #pragma unroll
    for (int j = 0; j < 4; j++){
        float b = __ldg(b_fh + (tx<<2) + j);
        #pragma unroll
        for (int i = 0; i < 4; i++) ff[i][j] = b;
    }
    #pragma unroll 4
    for (int e = 0; e < DD; e++){
        float4 hv = *(const float4*)(sHhat + e*HSTR + (ty<<2));
        float4 wv = *(const float4*)(sWf + e*64 + (tx<<2));
        float h[4] = {hv.x, hv.y, hv.z, hv.w};
        float w[4] = {wv.x, wv.y, wv.z, wv.w};
        #pragma unroll
        for (int i = 0; i < 4; i++)
            #pragma unroll
            for (int j = 0; j < 4; j++) ff[i][j] += h[i]*w[j];
    }
    #pragma unroll
    for (int j = 0; j < 4; j++){
        float fcp = 0.f;
        #pragma unroll
        for (int i = 0; i < 4; i++) fcp += sigf(ff[i][j]) * cst[i][j];
        atomicAdd(&sRed[     (tx<<2)+j], fcp);
        atomicAdd(&sRed[64 + (tx<<2)+j], hsb[j]);
    }
    __syncthreads();
    if (tid < 128) atomicAdd(&g_acc[tid], sRed[tid]);
}

__global__ void fin_kernel(const float* __restrict__ W_iouh, const float* __restrict__ b_iouh,
                           const float* __restrict__ W_oout, const float* __restrict__ b_oout,
                           float* __restrict__ out){
    __shared__ float sfc[64], shs[64], sho[64];
    int d = threadIdx.x;   // 0..63
    sfc[d] = g_acc[d];
    shs[d] = g_acc[64 + d];
    __syncthreads();
    float vi = b_iouh[d], vo = b_iouh[64 + d], vu = b_iouh[128 + d];
    #pragma unroll 8
    for (int e = 0; e < DD; e++){
        float h = shs[e];
        vi += h * W_iouh[(      d)*64 + e];
        vo += h * W_iouh[( 64 + d)*64 + e];
        vu += h * W_iouh[(128 + d)*64 + e];
    }
    float cobj = sigf(vi)*tanhp(vu) + sfc[d];
    sho[d] = sigf(vo)*tanhp(cobj);
    __syncthreads();
    float acc = b_oout[d];
    #pragma unroll 8
    for (int e = 0; e < DD; e++) acc += sho[e] * W_oout[d*64 + e];
    out[d]      = acc;
    out[64 + d] = cobj;
}

extern "C" void kernel_launch(void* const* d_in, const int* in_sizes, int n_in,
                              void* d_out, int out_size){
    const float* x      = (const float*)d_in[0];
    const float* W_num  = (const float*)d_in[1];
    const float* b_num  = (const float*)d_in[2];
    const float* W_ih   = (const float*)d_in[3];
    const float* W_hh   = (const float*)d_in[4];
    const float* b_ih   = (const float*)d_in[5];
    const float* b_hh   = (const float*)d_in[6];
    const float* W_aout = (const float*)d_in[7];
    const float* b_aout = (const float*)d_in[8];
    const float* W_fh   = (const float*)d_in[9];
    const float* b_fh   = (const float*)d_in[10];
    const float* W_iouh = (const float*)d_in[11];
    const float* b_iouh = (const float*)d_in[12];
    const float* W_oout = (const float*)d_in[13];
    const float* b_oout = (const float*)d_in[14];
    float* out = (float*)d_out;

    size_t smem = (16384 + 64*HSTR + 256 + 256 + 128) * sizeof(float);
    cudaFuncSetAttribute(lstm_kernel, cudaFuncAttributeMaxDynamicSharedMemorySize, (int)smem);

    prep_kernel<<<1, 256>>>(W_ih, W_num, b_num, b_ih, b_hh, W_hh);
    lstm_kernel<<<NBLK, 256, smem>>>(x, W_aout, b_aout, W_fh, b_fh);
    fin_kernel<<<1, 64>>>(W_iouh, b_iouh, W_oout, b_oout, out);
}

// round 2
// speedup vs baseline: 1.0197x; 1.0197x over previous
#include <cuda_runtime.h>
#include <cstdint>

#define DD 64
#define LL 128
#define KROWS 8192
#define RPB 64
#define NBLK (KROWS/RPB)
#define HSTR 68

typedef unsigned long long u64;

__device__ float g_a[256];
__device__ float g_cb[256];
__device__ float g_Wt[64*256];
__device__ float g_acc[128];

__device__ __forceinline__ float fexp(float x){
    x = fmaxf(fminf(x, 30.f), -30.f);
    return __expf(x);
}
__device__ __forceinline__ float sigf(float x){
    return __fdividef(1.0f, 1.0f + fexp(-x));
}
__device__ __forceinline__ float tanhp(float x){
    return 2.0f * __fdividef(1.0f, 1.0f + fexp(-2.0f*x)) - 1.0f;
}

__device__ __forceinline__ u64 pack2(float lo, float hi){
    u64 r; asm("mov.b64 %0, {%1, %2};" : "=l"(r) : "f"(lo), "f"(hi)); return r;
}
__device__ __forceinline__ float2 unpack2(u64 v){
    float2 r; asm("mov.b64 {%0, %1}, %2;" : "=f"(r.x), "=f"(r.y) : "l"(v)); return r;
}
__device__ __forceinline__ void ffma2(u64 &d, u64 a, u64 b){
    asm("fma.rn.f32x2 %0, %1, %2, %0;" : "+l"(d) : "l"(a), "l"(b));
}

// Precompute collapsed input projection + transposed W_hh + zero accumulators.
__global__ void prep_kernel(const float* __restrict__ W_ih, const float* __restrict__ W_num,
                            const float* __restrict__ b_num, const float* __restrict__ b_ih,
                            const float* __restrict__ b_hh, const float* __restrict__ W_hh){
    int g = threadIdx.x;   // 0..255
    float sa = 0.f, sc = 0.f;
    #pragma unroll 8
    for (int d = 0; d < DD; d++){
        float w = W_ih[g*(2*DD)+d];
        sa += w * W_num[d];
        sc += w * b_num[d];
    }
    g_a[g]  = sa;
    g_cb[g] = sc + b_ih[g] + b_hh[g];
    #pragma unroll 8
    for (int k = 0; k < DD; k++) g_Wt[k*256+g] = W_hh[g*DD+k];
    if (g < 128) g_acc[g] = 0.f;
}

__global__ void __launch_bounds__(256,1)
lstm_kernel(const float* __restrict__ x,
            const float* __restrict__ W_aout, const float* __restrict__ b_aout,
            const float* __restrict__ W_fh,  const float* __restrict__ b_fh){
    extern __shared__ float sm[];
    float* sWt  = sm;                  // 16384 floats: Wt[k][g]
    float* sH   = sm + 16384;          // 64*HSTR: h[d][r], stride HSTR
    float* sA   = sH + 64*HSTR;        // 256
    float* sC   = sA + 256;            // 256
    float* sRed = sC + 256;            // 128
    float* sX   = sRed + 128;          // 8192: x[r][t] for this CTA's 64 rows

    int tid = threadIdx.x;
    const int r0 = blockIdx.x * RPB;
    for (int i = tid; i < 16384;   i += 256) sWt[i] = g_Wt[i];
    for (int i = tid; i < 64*HSTR; i += 256) sH[i]  = 0.f;
    for (int i = tid; i < RPB*LL;  i += 256) sX[i]  = x[(size_t)r0*LL + i];
    sA[tid] = g_a[tid];
    sC[tid] = g_cb[tid];
    if (tid < 128) sRed[tid] = 0.f;
    __syncthreads();

    const int tx = tid & 15;       // d-tile: d = tx*4 + j
    const int ty = tid >> 4;       // r-tile: r = ty*4 + i

    float cst[4][4];
    #pragma unroll
    for (int i = 0; i < 4; i++)
        #pragma unroll
        for (int j = 0; j < 4; j++) cst[i][j] = 0.f;

    for (int t = 0; t < LL; t++){
        u64 ai[4][2], af[4][2], ag[4][2], ao[4][2];
        #pragma unroll
        for (int i = 0; i < 4; i++)
            #pragma unroll
            for (int jp = 0; jp < 2; jp++){ ai[i][jp]=0ull; af[i][jp]=0ull; ag[i][jp]=0ull; ao[i][jp]=0ull; }

        #pragma unroll 4
        for (int k = 0; k < DD; k++){
            float4 hv = *(const float4*)(sH + k*HSTR + (ty<<2));
            const u64* wr2 = (const u64*)(sWt + (k<<8));
            ulonglong2 wi = *(const ulonglong2*)(wr2 +      (tx<<1));
            ulonglong2 wf = *(const ulonglong2*)(wr2 + 32 + (tx<<1));
            ulonglong2 wg = *(const ulonglong2*)(wr2 + 64 + (tx<<1));
            ulonglong2 wo = *(const ulonglong2*)(wr2 + 96 + (tx<<1));
            u64 hp[4] = {pack2(hv.x,hv.x), pack2(hv.y,hv.y),
                         pack2(hv.z,hv.z), pack2(hv.w,hv.w)};
            #pragma unroll
            for (int i = 0; i < 4; i++){
                ffma2(ai[i][0], hp[i], wi.x);  ffma2(ai[i][1], hp[i], wi.y);
                ffma2(af[i][0], hp[i], wf.x);  ffma2(af[i][1], hp[i], wf.y);
                ffma2(ag[i][0], hp[i], wg.x);  ffma2(ag[i][1], hp[i], wg.y);
                ffma2(ao[i][0], hp[i], wo.x);  ffma2(ao[i][1], hp[i], wo.y);
            }
        }
        __syncthreads();   // all reads of sH done

        float hn[4][4];
        #pragma unroll
        for (int i = 0; i < 4; i++){
            float xv = sX[(((ty<<2)+i)<<7) + t];
            float aif[4], aff[4], agf[4], aof[4];
            {
                float2 p0 = unpack2(ai[i][0]), p1 = unpack2(ai[i][1]);
                aif[0]=p0.x; aif[1]=p0.y; aif[2]=p1.x; aif[3]=p1.y;
            }
            {
                float2 p0 = unpack2(af[i][0]), p1 = unpack2(af[i][1]);
                aff[0]=p0.x; aff[1]=p0.y; aff[2]=p1.x; aff[3]=p1.y;
            }
            {
                float2 p0 = unpack2(ag[i][0]), p1 = unpack2(ag[i][1]);
                agf[0]=p0.x; agf[1]=p0.y; agf[2]=p1.x; agf[3]=p1.y;
            }
            {
                float2 p0 = unpack2(ao[i][0]), p1 = unpack2(ao[i][1]);
                aof[0]=p0.x; aof[1]=p0.y; aof[2]=p1.x; aof[3]=p1.y;
            }
            #pragma unroll
            for (int j = 0; j < 4; j++){
                int d = (tx<<2) + j;
                float gi = aif[j] + sA[d      ]*xv + sC[d      ];
                float gf = aff[j] + sA[ 64 + d]*xv + sC[ 64 + d];
                float gg = agf[j] + sA[128 + d]*xv + sC[128 + d];
                float go = aof[j] + sA[192 + d]*xv + sC[192 + d];
                float c2 = sigf(gf)*cst[i][j] + sigf(gi)*tanhp(gg);
                cst[i][j] = c2;
                hn[i][j] = sigf(go)*tanhp(c2);
            }
        }
        #pragma unroll
        for (int j = 0; j < 4; j++){
            *(float4*)(sH + ((tx<<2)+j)*HSTR + (ty<<2)) =
                make_float4(hn[0][j], hn[1][j], hn[2][j], hn[3][j]);
        }
        __syncthreads();
    }

    // ----- final per-CTA stage: h_hat, f, partial reductions -----
    float* sHhat = sWt;            // [e][r] stride HSTR
    float* sWa   = sWt + 8192;     // W_aout transposed: [e][d]
    float* sWf   = sWt + 12288;    // W_fh  transposed: [e][d]
    for (int i = tid; i < 4096; i += 256){
        int dd = i & 63;
        int ee = i >> 6;
        sWa[i] = W_aout[dd*64 + ee];
        sWf[i] = W_fh  [dd*64 + ee];
    }
    __syncthreads();

    // h_hat[r][d] = sum_e h[r][e] * W_aout[d][e] + b_aout[d]
    float hh[4][4];
    #pragma unroll
    for (int j = 0; j < 4; j++){
        float b = __ldg(b_aout + (tx<<2) + j);
        #pragma unroll
        for (int i = 0; i < 4; i++) hh[i][j] = b;
    }
    #pragma unroll 4
    for (int e = 0; e < DD; e++){
        float4 hv = *(const float4*)(sH + e*HSTR + (ty<<2));
        float4 wv = *(const float4*)(sWa + e*64 + (tx<<2));
        float h[4] = {hv.x, hv.y, hv.z, hv.w};
        float w[4] = {wv.x, wv.y, wv.z, wv.w};
        #pragma unroll
        for (int i = 0; i < 4; i++)
            #pragma unroll
            for (int j = 0; j < 4; j++) hh[i][j] += h[i]*w[j];
    }
    float hsb[4];
    #pragma unroll
    for (int j = 0; j < 4; j++){
        hsb[j] = hh[0][j] + hh[1][j] + hh[2][j] + hh[3][j];
        *(float4*)(sHhat + ((tx<<2)+j)*HSTR + (ty<<2)) =
            make_float4(hh[0][j], hh[1][j], hh[2][j], hh[3][j]);
    }
    __syncthreads();

    // f[r][d] = sum_e h_hat[r][e] * W_fh[d][e] + b_fh[d]
    float ff[4][4];
    #pragma unroll
    for (int j = 0; j < 4; j++){
        float b = __ldg(b_fh + (tx<<2) + j);
        #pragma unroll
        for (int i = 0; i < 4; i++) ff[i][j] = b;
    }
    #pragma unroll 4
    for (int e = 0; e < DD; e++){
        float4 hv = *(const float4*)(sHhat + e*HSTR + (ty<<2));
        float4 wv = *(const float4*)(sWf + e*64 + (tx<<2));
        float h[4] = {hv.x, hv.y, hv.z, hv.w};
        float w[4] = {wv.x, wv.y, wv.z, wv.w};
        #pragma unroll
        for (int i = 0; i < 4; i++)
            #pragma unroll
            for (int j = 0; j < 4; j++) ff[i][j] += h[i]*w[j];
    }
    #pragma unroll
    for (int j = 0; j < 4; j++){
        float fcp = 0.f;
        #pragma unroll
        for (int i = 0; i < 4; i++) fcp += sigf(ff[i][j]) * cst[i][j];
        atomicAdd(&sRed[     (tx<<2)+j], fcp);
        atomicAdd(&sRed[64 + (tx<<2)+j], hsb[j]);
    }
    __syncthreads();
    if (tid < 128) atomicAdd(&g_acc[tid], sRed[tid]);
}

__global__ void fin_kernel(const float* __restrict__ W_iouh, const float* __restrict__ b_iouh,
                           const float* __restrict__ W_oout, const float* __restrict__ b_oout,
                           float* __restrict__ out){
    __shared__ float sfc[64], shs[64], sho[64];
    int d = threadIdx.x;   // 0..63
    sfc[d] = g_acc[d];
    shs[d] = g_acc[64 + d];
    __syncthreads();
    float vi = b_iouh[d], vo = b_iouh[64 + d], vu = b_iouh[128 + d];
    #pragma unroll 8
    for (int e = 0; e < DD; e++){
        float h = shs[e];
        vi += h * W_iouh[(      d)*64 + e];
        vo += h * W_iouh[( 64 + d)*64 + e];
        vu += h * W_iouh[(128 + d)*64 + e];
    }
    float cobj = sigf(vi)*tanhp(vu) + sfc[d];
    sho[d] = sigf(vo)*tanhp(cobj);
    __syncthreads();
    float acc = b_oout[d];
    #pragma unroll 8
    for (int e = 0; e < DD; e++) acc += sho[e] * W_oout[d*64 + e];
    out[d]      = acc;
    out[64 + d] = cobj;
}

extern "C" void kernel_launch(void* const* d_in, const int* in_sizes, int n_in,
                              void* d_out, int out_size){
    const float* x      = (const float*)d_in[0];
    const float* W_num  = (const float*)d_in[1];
    const float* b_num  = (const float*)d_in[2];
    const float* W_ih   = (const float*)d_in[3];
    const float* W_hh   = (const float*)d_in[4];
    const float* b_ih   = (const float*)d_in[5];
    const float* b_hh   = (const float*)d_in[6];
    const float* W_aout = (const float*)d_in[7];
    const float* b_aout = (const float*)d_in[8];
    const float* W_fh   = (const float*)d_in[9];
    const float* b_fh   = (const float*)d_in[10];
    const float* W_iouh = (const float*)d_in[11];
    const float* b_iouh = (const float*)d_in[12];
    const float* W_oout = (const float*)d_in[13];
    const float* b_oout = (const float*)d_in[14];
    float* out = (float*)d_out;

    size_t smem = (16384 + 64*HSTR + 256 + 256 + 128 + 8192) * sizeof(float);
    cudaFuncSetAttribute(lstm_kernel, cudaFuncAttributeMaxDynamicSharedMemorySize, (int)smem);

    prep_kernel<<<1, 256>>>(W_ih, W_num, b_num, b_ih, b_hh, W_hh);
    lstm_kernel<<<NBLK, 256, smem>>>(x, W_aout, b_aout, W_fh, b_fh);
    fin_kernel<<<1, 64>>>(W_iouh, b_iouh, W_oout, b_oout, out);
}